// round 1
// baseline (speedup 1.0000x reference)
#include <cuda_runtime.h>

#define DDIM 256
#define MT 128          // rows per block tile
#define KT 128          // codes per k-chunk
#define DC 32           // depth per inner chunk
#define MAXBLK 512      // 65536/128

__device__ float g_cnorm[1024];
__device__ float g_partial[MAXBLK];

// swizzled transposed tile index: layout [d][m], m xor'd by (d>>2)&7 in float4 units
__device__ __forceinline__ int sw_idx(int d, int m) {
    return d * 128 + (m ^ (((d >> 2) & 7) << 2));
}

__global__ void cnorm_kernel(const float* __restrict__ w, int K) {
    int k = blockIdx.x * 8 + (threadIdx.x >> 5);
    int lane = threadIdx.x & 31;
    if (k >= K) return;
    const float4* wr = (const float4*)(w + (size_t)k * DDIM);
    float4 v0 = wr[lane];
    float4 v1 = wr[lane + 32];
    float s = v0.x*v0.x + v0.y*v0.y + v0.z*v0.z + v0.w*v0.w
            + v1.x*v1.x + v1.y*v1.y + v1.z*v1.z + v1.w*v1.w;
    #pragma unroll
    for (int m = 16; m; m >>= 1) s += __shfl_xor_sync(0xffffffffu, s, m);
    if (lane == 0) g_cnorm[k] = s;
}

__global__ __launch_bounds__(256, 2)
void vq_kernel(const float* __restrict__ z, const float* __restrict__ w,
               float* __restrict__ out, int N, int K)
{
    __shared__ __align__(16) float zs[DC * MT];
    __shared__ __align__(16) float ws[DC * KT];
    __shared__ float s_minval[MT];
    __shared__ int   s_minidx[MT];
    __shared__ float s_cn[KT];
    __shared__ float s_red[256];

    const int tid = threadIdx.x;
    const int tx = tid & 15;
    const int ty = tid >> 4;
    const int rowBase = blockIdx.x * MT;

    if (tid < MT) { s_minval[tid] = 3.4e38f; s_minidx[tid] = 0; }
    __syncthreads();

    const int m0 = ty * 4;          // fragment row groups
    const int m1 = 64 + ty * 4;
    const int c0 = tx * 4;          // fragment code groups
    const int c1 = 64 + tx * 4;

    for (int kc = 0; kc < K; kc += KT) {
        float acc[8][8];
        #pragma unroll
        for (int i = 0; i < 8; i++)
            #pragma unroll
            for (int j = 0; j < 8; j++) acc[i][j] = 0.f;

        if (tid < KT) s_cn[tid] = g_cnorm[kc + tid];

        for (int dc = 0; dc < DDIM; dc += DC) {
            // cooperative load + transpose of both tiles (swizzled, conflict-free)
            #pragma unroll
            for (int it = 0; it < 4; it++) {
                int q   = tid + 256 * it;   // float4 slot 0..1023
                int row = q >> 3;           // 8 float4 per row of DC=32
                int c4  = q & 7;
                int db  = c4 * 4;
                float4 v = *(const float4*)(z + (size_t)(rowBase + row) * DDIM + dc + c4 * 4);
                zs[sw_idx(db + 0, row)] = v.x;
                zs[sw_idx(db + 1, row)] = v.y;
                zs[sw_idx(db + 2, row)] = v.z;
                zs[sw_idx(db + 3, row)] = v.w;
                float4 u = *(const float4*)(w + (size_t)(kc + row) * DDIM + dc + c4 * 4);
                ws[sw_idx(db + 0, row)] = u.x;
                ws[sw_idx(db + 1, row)] = u.y;
                ws[sw_idx(db + 2, row)] = u.z;
                ws[sw_idx(db + 3, row)] = u.w;
            }
            __syncthreads();

            #pragma unroll
            for (int d = 0; d < DC; d++) {
                float4 a0 = *(const float4*)&zs[sw_idx(d, m0)];
                float4 a1 = *(const float4*)&zs[sw_idx(d, m1)];
                float4 b0 = *(const float4*)&ws[sw_idx(d, c0)];
                float4 b1 = *(const float4*)&ws[sw_idx(d, c1)];
                float a[8] = {a0.x, a0.y, a0.z, a0.w, a1.x, a1.y, a1.z, a1.w};
                float b[8] = {b0.x, b0.y, b0.z, b0.w, b1.x, b1.y, b1.z, b1.w};
                #pragma unroll
                for (int i = 0; i < 8; i++)
                    #pragma unroll
                    for (int j = 0; j < 8; j++)
                        acc[i][j] = fmaf(a[i], b[j], acc[i][j]);
            }
            __syncthreads();
        }

        // scores: s = ||e||^2 - 2*dot ; row-wise argmin with lowest-index tie-break
        #pragma unroll
        for (int i = 0; i < 8; i++) {
            float bv = 3.4e38f;
            int   bi = 0x7fffffff;
            #pragma unroll
            for (int j = 0; j < 8; j++) {
                int cl = (j < 4) ? (c0 + j) : (c1 + j - 4);   // ascending in j
                float s = fmaf(-2.f, acc[i][j], s_cn[cl]);
                int code = kc + cl;
                if (s < bv) { bv = s; bi = code; }            // strict <: keeps lowest idx
            }
            #pragma unroll
            for (int md = 8; md; md >>= 1) {
                float ov = __shfl_xor_sync(0xffffffffu, bv, md, 16);
                int   oi = __shfl_xor_sync(0xffffffffu, bi, md, 16);
                if (ov < bv || (ov == bv && oi < bi)) { bv = ov; bi = oi; }
            }
            if (tx == 0) {
                int row = (i < 4) ? (m0 + i) : (m1 + i - 4);
                if (bv < s_minval[row] || (bv == s_minval[row] && bi < s_minidx[row])) {
                    s_minval[row] = bv;
                    s_minidx[row] = bi;
                }
            }
        }
        __syncthreads();   // protect s_cn / s_minval before next chunk
    }

    // ---- epilogue: write z_q, indices, accumulate loss partial ----
    float* out_zq  = out + 1;
    float* out_idx = out + 1 + (size_t)N * DDIM;

    int row  = tid >> 1;
    int half = tid & 1;
    int gRow = rowBase + row;
    int idx  = s_minidx[row];
    if (half == 0) out_idx[gRow] = (float)idx;

    const float* wr   = w + (size_t)idx  * DDIM + half * 128;
    const float* zr   = z + (size_t)gRow * DDIM + half * 128;
    float*       orow = out_zq + (size_t)gRow * DDIM + half * 128;

    float lsum = 0.f;
    #pragma unroll 8
    for (int v = 0; v < 32; v++) {
        float4 wv = *(const float4*)(wr + v * 4);
        float4 zv = *(const float4*)(zr + v * 4);
        float d0 = wv.x - zv.x, d1 = wv.y - zv.y, d2 = wv.z - zv.z, d3 = wv.w - zv.w;
        lsum += d0*d0 + d1*d1 + d2*d2 + d3*d3;
        // out+1 base is not 16B aligned -> scalar stores
        orow[v*4 + 0] = wv.x;
        orow[v*4 + 1] = wv.y;
        orow[v*4 + 2] = wv.z;
        orow[v*4 + 3] = wv.w;
    }

    s_red[tid] = lsum;
    __syncthreads();
    #pragma unroll
    for (int m = 128; m; m >>= 1) {
        if (tid < m) s_red[tid] += s_red[tid + m];
        __syncthreads();
    }
    if (tid == 0) g_partial[blockIdx.x] = s_red[0];
}

__global__ void finalize_kernel(float* __restrict__ out, int nblocks, float scale) {
    __shared__ float s[512];
    int t = threadIdx.x;
    s[t] = (t < nblocks) ? g_partial[t] : 0.f;
    __syncthreads();
    #pragma unroll
    for (int m = 256; m; m >>= 1) {
        if (t < m) s[t] += s[t + m];
        __syncthreads();
    }
    if (t == 0) out[0] = s[0] * scale;
}

extern "C" void kernel_launch(void* const* d_in, const int* in_sizes, int n_in,
                              void* d_out, int out_size) {
    const float* z = (const float*)d_in[0];
    const float* w = (const float*)d_in[1];
    float* out = (float*)d_out;

    int N = in_sizes[0] / DDIM;   // 65536
    int K = in_sizes[1] / DDIM;   // 1024

    cnorm_kernel<<<(K + 7) / 8, 256>>>(w, K);
    vq_kernel<<<N / MT, 256>>>(z, w, out, N, K);
    // loss = BETA * mean((z_q - z)^2), BETA = 0.25
    float scale = 0.25f / ((float)N * (float)DDIM);
    finalize_kernel<<<1, 512>>>(out, N / MT, scale);
}